// round 16
// baseline (speedup 1.0000x reference)
#include <cuda_runtime.h>
#include <math.h>

// HamiltonianFlow: dq/dt = p, dp/dt = -(q + q^3) — Duffing oscillator, exact.
//   E = p^2/2 + q^2/2 + q^4/4,  r1 = sqrt(1+4E) = 1+A^2 = omega^2,
//   m = (1 - 1/r1)/2 < 1/2,  q(t) = A cn(u0 + omega t, k).
// Sqrt-free initial data: the Jacobi addition theorem at u0+b only needs
//   A cn0 = q0,  A sn0 dn0 = -p0/omega = -P,  cn0^2 = q0^2/A^2,
//   sn0^2 = 1-cn0^2,  dn0^2 = 1 - m sn0^2  — all algebraic in (q0,p0):
//   qT = D (q0 cb + P sb db)
//   pT = -omega D^2 [ -P cb db^2 + sb ( q0 db (1 - msq (1+cb^2))
//                                       + m P cn0sq sb cb ) ],  msq = m sn0^2
// Shift b = 10*omega via Landen (k1 exact, k2/k3 series, Cody-Waite trig
// bottom, 2 ascend levels). Single-MUFU .approx roots/recips.
// 2 pairs/thread (ILP-2), block 128, 1024 blocks.

__device__ __forceinline__ float fsqrt_ap(float x) {
    float r; asm("sqrt.approx.f32 %0, %1;" : "=f"(r) : "f"(x)); return r;
}
__device__ __forceinline__ float frcp_ap(float x) {
    float r; asm("rcp.approx.f32 %0, %1;" : "=f"(r) : "f"(x)); return r;
}
__device__ __forceinline__ float frsqrt_ap(float x) {
    float r; asm("rsqrt.approx.f32 %0, %1;" : "=f"(r) : "f"(x)); return r;
}

__device__ __forceinline__ float2 duffing_exact(float q0, float p0) {
    // ---- energy, frequency, modulus ----
    float q2 = q0 * q0;
    float E  = fmaf(0.5f * p0, p0, fmaf(0.25f * q2, q2, 0.5f * q2));
    float r1 = fsqrt_ap(fmaf(4.0f, E, 1.0f));        // = 1 + A^2 = omega^2
    float A2 = fmaxf(r1 - 1.0f, 1e-12f);
    float rsq = frsqrt_ap(r1);                       // = 1/omega
    float omega = r1 * rsq;
    float m     = fmaf(-0.5f * rsq, rsq, 0.5f);      // (1 - 1/r1)/2 in (0,.5)

    // ---- sqrt-free initial data ----
    float cn0sq = fminf(q2 * frcp_ap(A2), 1.0f);     // cn0^2 = q0^2/A^2
    float sn0sq = 1.0f - cn0sq;
    float msq   = m * sn0sq;
    float P     = p0 * rsq;                          // p0/omega

    // ---- Landen moduli: k1 exact, k2/k3 by series ----
    float kp  = fsqrt_ap(1.0f - m);                  // >= 0.707
    float k1  = (1.0f - kp) * frcp_ap(1.0f + kp);    // <= 0.172
    float t   = k1 * k1;                             // <= 0.0295
    float k2  = 0.25f * t * fmaf(t, fmaf(0.34375f, t, 0.5f), 1.0f); // <=7.4e-3
    float k3  = 0.25f * k2 * k2;                     // <= 1.4e-5
    float Pfac = (1.0f + k1) * (1.0f + (k2 + k3));   // 2K/pi

    // ---- forward evaluation at b = 10*omega ----
    float v = 10.0f * omega * frcp_ap(Pfac);         // <= ~50
    const float INV2PI = 0.15915494309189535f;
    const float PI2_HI = 6.28125f;                   // exact in fp32
    const float PI2_LO = 1.9353071795864769e-3f;
    float nn = rintf(v * INV2PI);
    float r  = fmaf(-nn, PI2_HI, v);
    r = fmaf(-nn, PI2_LO, r);
    float sn = __sinf(r), cn = __cosf(r);            // level-2 (dn = 1)

    // ascend k2: 1/(1+x) ~= 1 - x + x^2  (x <= 7.4e-3)
    float x2   = k2 * sn * sn;
    float rd2  = fmaf(x2, x2, 1.0f) - x2;
    float sn1  = (1.0f + k2) * sn * rd2;
    float cn1  = cn * rd2;
    float dn1  = (1.0f - x2) * rd2;

    // ascend k1: full reciprocal (x up to 0.172)
    float x1   = k1 * sn1 * sn1;
    float rd1  = frcp_ap(1.0f + x1);
    float sb   = (1.0f + k1) * sn1 * rd1;
    float cb   = cn1 * dn1 * rd1;
    float db   = (1.0f - x1) * rd1;

    // ---- sqrt-free addition theorem ----
    float sb2  = sb * sb;
    float cb2  = cb * cb;
    float D    = frcp_ap(fmaf(-msq, sb2, 1.0f));
    float sbdb = sb * db;

    float qT = D * fmaf(P, sbdb, q0 * cb);

    // S = -P cb db^2 + sb [ q0 db (1 - msq (1+cb^2)) + m P cn0sq sb cb ]
    float inner = fmaf(-msq, 1.0f + cb2, 1.0f);      // dn0^2 - msq cb^2
    float br    = fmaf((m * P) * cn0sq, sb * cb, (q0 * inner) * db);
    float S     = fmaf(-P * cb, db * db, sb * br);
    float pT    = -omega * (D * D) * S;

    return make_float2(qT, pT);
}

__global__ __launch_bounds__(128) void ham_exact_kernel(
    const float4* __restrict__ in, float4* __restrict__ out, int n4)
{
    int i = blockIdx.x * blockDim.x + threadIdx.x;
    if (i >= n4) return;

    float4 v = in[i];                  // two independent (q,p) pairs
    float2 a = duffing_exact(v.x, v.y);
    float2 b = duffing_exact(v.z, v.w);
    out[i] = make_float4(a.x, a.y, b.x, b.y);
}

extern "C" void kernel_launch(void* const* d_in, const int* in_sizes, int n_in,
                              void* d_out, int out_size) {
    const float4* in = (const float4*)d_in[0];
    float4* out = (float4*)d_out;
    int n4 = in_sizes[0] / 4;              // 131072 float4 = 2 pairs each
    int block = 128;
    int grid = (n4 + block - 1) / block;   // 1024 blocks over 148 SMs
    ham_exact_kernel<<<grid, block>>>(in, out, n4);
}

// round 17
// speedup vs baseline: 1.0386x; 1.0386x over previous
#include <cuda_runtime.h>
#include <math.h>

// HamiltonianFlow: dq/dt = p, dp/dt = -(q + q^3) — Duffing oscillator, exact.
//   E = p^2/2 + q^2/2 + q^4/4,  r1 = sqrt(1+4E) = 1+A^2 = omega^2,
//   m = (1 - 1/r1)/2 < 1/2,  q(t) = A cn(u0 + omega t, k).
// Sqrt-free initial data (addition theorem needs only algebraic combos):
//   A cn0 = q0,  A sn0 dn0 = -P (P = p0/omega),  cn0^2 = q0^2/A^2.
// Shift b = 10*omega via Landen: k1 exact, k2/k3 series; trig bottom fed
// DIRECTLY to __sinf/__cosf (HW RRO range reduction, |err| ~ 1.2e-5 rad at
// v<=50); level-2 ascend to first order in k2 (err <= 2*k2^2*sn^2, tail-only);
// level-1 ascend exact with one MUFU rcp. Single-MUFU .approx roots/recips.
// 2 pairs/thread (ILP-2), block 128, 1024 blocks.

__device__ __forceinline__ float fsqrt_ap(float x) {
    float r; asm("sqrt.approx.f32 %0, %1;" : "=f"(r) : "f"(x)); return r;
}
__device__ __forceinline__ float frcp_ap(float x) {
    float r; asm("rcp.approx.f32 %0, %1;" : "=f"(r) : "f"(x)); return r;
}
__device__ __forceinline__ float frsqrt_ap(float x) {
    float r; asm("rsqrt.approx.f32 %0, %1;" : "=f"(r) : "f"(x)); return r;
}

__device__ __forceinline__ float2 duffing_exact(float q0, float p0) {
    // ---- energy, frequency, modulus ----
    float q2 = q0 * q0;
    float E  = fmaf(0.5f * p0, p0, fmaf(0.25f * q2, q2, 0.5f * q2));
    float r1 = fsqrt_ap(fmaf(4.0f, E, 1.0f));        // = 1 + A^2 = omega^2
    float A2 = fmaxf(r1 - 1.0f, 1e-12f);
    float rsq = frsqrt_ap(r1);                       // = 1/omega
    float omega = r1 * rsq;
    float m     = fmaf(-0.5f * rsq, rsq, 0.5f);      // (1 - 1/r1)/2 in (0,.5)

    // ---- sqrt-free initial data ----
    float cn0sq = fminf(q2 * frcp_ap(A2), 1.0f);     // cn0^2 = q0^2/A^2
    float sn0sq = 1.0f - cn0sq;
    float msq   = m * sn0sq;
    float P     = p0 * rsq;                          // p0/omega

    // ---- Landen moduli: k1 exact, k2/k3 by series ----
    float kp  = fsqrt_ap(1.0f - m);                  // >= 0.707
    float k1  = (1.0f - kp) * frcp_ap(1.0f + kp);    // <= 0.172
    float t   = k1 * k1;                             // <= 0.0295
    float k2  = 0.25f * t * fmaf(t, fmaf(0.34375f, t, 0.5f), 1.0f); // <=7.4e-3
    float k3  = 0.25f * k2 * k2;                     // <= 1.4e-5
    float Pfac = (1.0f + k1) * (1.0f + (k2 + k3));   // 2K/pi

    // ---- forward: b = 10*omega; HW RRO handles v mod 2pi ----
    float v  = 10.0f * omega * frcp_ap(Pfac);        // <= ~50 rad
    float sn = __sinf(v), cn = __cosf(v);            // level-2 (dn = 1)

    // ascend k2, first order (x2 = k2 sn^2 <= 7.4e-3):
    //   sn1 = sn + k2 sn (1 - sn^2),  cn1 = cn (1 - k2 sn^2),  dn1 = 1 - 2 k2 sn^2
    float s2  = sn * sn;
    float u   = k2 * s2;
    float sn1 = fmaf(k2 * sn, 1.0f - s2, sn);
    float cn1 = fmaf(-u, cn, cn);
    float dn1 = fmaf(-2.0f, u, 1.0f);

    // ascend k1: exact (x1 up to 0.172)
    float x1  = k1 * sn1 * sn1;
    float rd1 = frcp_ap(1.0f + x1);
    float sb  = (1.0f + k1) * sn1 * rd1;
    float cb  = cn1 * dn1 * rd1;
    float db  = (1.0f - x1) * rd1;

    // ---- sqrt-free addition theorem ----
    float sb2  = sb * sb;
    float cb2  = cb * cb;
    float D    = frcp_ap(fmaf(-msq, sb2, 1.0f));
    float sbdb = sb * db;

    float qT = D * fmaf(P, sbdb, q0 * cb);

    // S = -P cb db^2 + sb [ q0 db (1 - msq (1+cb^2)) + m P cn0sq sb cb ]
    float inner = fmaf(-msq, 1.0f + cb2, 1.0f);
    float br    = fmaf((m * P) * cn0sq, sb * cb, (q0 * inner) * db);
    float S     = fmaf(-P * cb, db * db, sb * br);
    float pT    = -omega * (D * D) * S;

    return make_float2(qT, pT);
}

__global__ __launch_bounds__(128) void ham_exact_kernel(
    const float4* __restrict__ in, float4* __restrict__ out, int n4)
{
    int i = blockIdx.x * blockDim.x + threadIdx.x;
    if (i >= n4) return;

    float4 v = in[i];                  // two independent (q,p) pairs
    float2 a = duffing_exact(v.x, v.y);
    float2 b = duffing_exact(v.z, v.w);
    out[i] = make_float4(a.x, a.y, b.x, b.y);
}

extern "C" void kernel_launch(void* const* d_in, const int* in_sizes, int n_in,
                              void* d_out, int out_size) {
    const float4* in = (const float4*)d_in[0];
    float4* out = (float4*)d_out;
    int n4 = in_sizes[0] / 4;              // 131072 float4 = 2 pairs each
    int block = 128;
    int grid = (n4 + block - 1) / block;   // 1024 blocks over 148 SMs
    ham_exact_kernel<<<grid, block>>>(in, out, n4);
}